// round 1
// baseline (speedup 1.0000x reference)
#include <cuda_runtime.h>
#include <math.h>

// Problem constants (from reference)
#define T_MAX 2000
#define B_N   64
#define A_N   32
#define L_N   200
#define S_N   401   // 2*L + 1

// Per-batch logaddexp(f0,f1) results (no cudaMalloc allowed)
__device__ float d_per_batch[B_N];

#define NTHREADS 128
#define STATES_PER_THREAD 4   // 128*4 = 512 >= 401

__global__ __launch_bounds__(NTHREADS, 1)
void ctc_alpha_kernel(const float* __restrict__ pred,      // (T,B,A) log-softmax
                      const int*   __restrict__ target,    // (B,L)
                      const int*   __restrict__ pred_lens, // (B,)
                      const int*   __restrict__ target_lens)
{
    const int b   = blockIdx.x;
    const int tid = threadIdx.x;

    __shared__ float alpha[2][S_N];
    __shared__ float row[2][A_N];
    __shared__ int   sym[L_N];

    // Load target symbols for this batch
    for (int i = tid; i < L_N; i += NTHREADS)
        sym[i] = target[b * L_N + i];

    const int Tb = pred_lens[b];

    // alpha0
    const float LOG_EPS  = logf(0.0001f);
    const float LOG_HALF = logf(0.499f);
    for (int s = tid; s < S_N; s += NTHREADS)
        alpha[0][s] = (s < 2) ? LOG_HALF : LOG_EPS;

    // Preload logit row for t=1 into row[1]
    if (tid < A_N && Tb > 1)
        row[1][tid] = pred[(size_t)(1 * B_N + b) * A_N + tid];

    __syncthreads();

    // Per-state precompute (after sym is loaded)
    int   esel[STATES_PER_THREAD];
    bool  has[STATES_PER_THREAD];
    bool  has1[STATES_PER_THREAD];  // include a[s-1]
    bool  has2[STATES_PER_THREAD];  // include a[s-2] (skip transition)
    #pragma unroll
    for (int k = 0; k < STATES_PER_THREAD; k++) {
        int s = tid + NTHREADS * k;
        has[k] = (s < S_N);
        if (has[k]) {
            esel[k] = (s & 1) ? sym[(s - 1) >> 1] : 0;
            has1[k] = (s >= 1);
            has2[k] = ((s & 1) && s >= 3);
        } else {
            esel[k] = 0; has1[k] = false; has2[k] = false;
        }
    }

    const float NEG_BIG = -1e30f;
    const size_t stride_t = (size_t)B_N * A_N;
    const float* pred_b = pred + (size_t)b * A_N;

    int cur = 0;
    for (int t = 1; t < Tb; ++t) {
        const int nxt = cur ^ 1;

        // Prefetch row for t+1 (overlaps with compute below)
        float pf = 0.0f;
        const bool do_pf = (tid < A_N) && (t + 1 < Tb);
        if (do_pf)
            pf = pred_b[(size_t)(t + 1) * stride_t + tid];

        const float* __restrict__ rc = row[t & 1];
        const float* __restrict__ ac = alpha[cur];
        float*       __restrict__ an = alpha[nxt];

        #pragma unroll
        for (int k = 0; k < STATES_PER_THREAD; k++) {
            if (!has[k]) continue;
            int s = tid + NTHREADS * k;
            float a0 = ac[s];
            float a1 = has1[k] ? ac[s - 1] : NEG_BIG;
            float a2 = has2[k] ? ac[s - 2] : NEG_BIG;
            float m  = fmaxf(fmaxf(a0, a1), a2);
            float sum = __expf(a0 - m) + __expf(a1 - m) + __expf(a2 - m);
            an[s] = rc[esel[k]] + m + __logf(sum);
        }

        if (do_pf)
            row[(t + 1) & 1][tid] = pf;

        __syncthreads();
        cur = nxt;
    }

    if (tid == 0) {
        int tl = target_lens[b];
        int sid = 2 * tl;                 // tl in [100,200] -> sid in [200,400]
        float f0 = alpha[cur][sid - 1];
        float f1 = alpha[cur][sid];
        float m  = fmaxf(f0, f1);
        d_per_batch[b] = m + log1pf(expf(fminf(f0, f1) - m));
    }
}

__global__ void ctc_reduce_kernel(float* __restrict__ out)
{
    const int tid = threadIdx.x;   // 64 threads
    float v = d_per_batch[tid];
    __shared__ float ws[2];
    #pragma unroll
    for (int o = 16; o > 0; o >>= 1)
        v += __shfl_down_sync(0xffffffffu, v, o);
    if ((tid & 31) == 0) ws[tid >> 5] = v;
    __syncthreads();
    if (tid == 0)
        out[0] = -(ws[0] + ws[1]) * (1.0f / (float)B_N);
}

extern "C" void kernel_launch(void* const* d_in, const int* in_sizes, int n_in,
                              void* d_out, int out_size)
{
    const float* prediction  = (const float*)d_in[0];  // (T,B,A) f32
    const int*   target      = (const int*)  d_in[1];  // (B,L) i32
    const int*   pred_lens   = (const int*)  d_in[2];  // (B,) i32
    const int*   target_lens = (const int*)  d_in[3];  // (B,) i32
    float* out = (float*)d_out;

    ctc_alpha_kernel<<<B_N, NTHREADS>>>(prediction, target, pred_lens, target_lens);
    ctc_reduce_kernel<<<1, B_N>>>(out);
}

// round 3
// speedup vs baseline: 2.9538x; 2.9538x over previous
#include <cuda_runtime.h>
#include <math.h>

#define T_MAX 2000
#define B_N   64
#define A_N   32
#define L_N   200
#define S_N   401          // 2*L+1
#define S_PAD 514          // 512 states + 2 sentinel slots

#define NTHREADS 256
#define SPT 2              // states per thread: 256*2 = 512 >= 401
#define PF 8               // prefetch group depth (rows per LDG burst)

__device__ float d_per_batch[B_N];

__device__ __forceinline__ float ex2(float x) {
    float r; asm("ex2.approx.ftz.f32 %0, %1;" : "=f"(r) : "f"(x)); return r;
}
__device__ __forceinline__ float lg2(float x) {
    float r; asm("lg2.approx.ftz.f32 %0, %1;" : "=f"(r) : "f"(x)); return r;
}

__global__ __launch_bounds__(NTHREADS, 1)
void ctc_alpha_kernel(const float* __restrict__ pred,      // (T,B,A) log-softmax
                      const int*   __restrict__ target,    // (B,L)
                      const int*   __restrict__ pred_lens,
                      const int*   __restrict__ target_lens)
{
    const int b     = blockIdx.x;
    const int tid   = threadIdx.x;
    const int slotp = tid >> 5;      // 0..7  (which row of the group this thread loads)
    const int lane  = tid & 31;

    __shared__ float alpha[2][S_PAD];   // +2 index shift; [0],[1] = NEG_BIG sentinels
    __shared__ float rows[2][PF * A_N]; // double-buffered e-rows, log2 domain
    __shared__ int   sym[L_N];

    const float LOG2E   = 1.4426950408889634f;
    const float LN2     = 0.6931471805599453f;
    const float NEG_BIG = -1e30f;

    for (int i = tid; i < L_N; i += NTHREADS)
        sym[i] = target[b * L_N + i];

    const int Tb = pred_lens[b];
    const size_t stride_t = (size_t)B_N * A_N;
    const float* __restrict__ pred_b = pred + (size_t)b * A_N;

    // alpha0 (log2 domain); sentinels at [0],[1]
    const float L2_EPS  = -13.287712379549449f;  // log2(0.0001)
    const float L2_HALF = -1.0028901240599430f;  // log2(0.499)
    for (int s = tid; s < S_PAD; s += NTHREADS) {
        float v = (s < 2) ? NEG_BIG : ((s < 4) ? L2_HALF : L2_EPS);
        alpha[0][s] = v;
        alpha[1][s] = (s < 2) ? NEG_BIG : 0.0f;
    }

    // Group 0 (rows 1..8) straight to shared
    rows[0][tid] = pred_b[(size_t)min(1 + slotp, T_MAX - 1) * stride_t + lane] * LOG2E;
    // Group 1 (rows 9..16): raw load held in register; scaled at commit time
    float pf_reg = pred_b[(size_t)min(9 + slotp, T_MAX - 1) * stride_t + lane];
    __syncthreads();

    // Per-state constants (states s = tid, tid + 256)
    int  esel[SPT];
    bool skip2[SPT];
    #pragma unroll
    for (int k = 0; k < SPT; k++) {
        int s = tid + NTHREADS * k;
        int li = (s - 1) >> 1;
        esel[k]  = ((s & 1) && li < L_N) ? sym[li] : 0;
        skip2[k] = ((s & 1) && s >= 3);
    }

    int cur = 0, phase = 0;
    for (int t = 1; t < Tb; ++t) {
        const int nxt  = cur ^ 1;
        const int slot = (t - 1) & (PF - 1);

        const float* __restrict__ rc = &rows[phase][slot * A_N];
        const float* __restrict__ Ac = alpha[cur];
        float*       __restrict__ An = alpha[nxt];

        #pragma unroll
        for (int k = 0; k < SPT; k++) {
            const int s = tid + NTHREADS * k;
            float a0 = Ac[s + 2];
            float a1 = Ac[s + 1];
            float a2 = skip2[k] ? Ac[s] : NEG_BIG;
            float hi = fmaxf(a0, a1);
            float lo = fminf(a0, a1);
            float m  = fmaxf(hi, a2);
            float mi = fminf(hi, a2);
            float sum = 1.0f + ex2(mi - m) + ex2(lo - m);
            An[s + 2] = rc[esel[k]] + m + lg2(sum);
        }

        if (slot == PF - 1) {
            // Commit group held in register ~7 steps (DRAM latency fully covered)
            rows[phase ^ 1][tid] = pf_reg * LOG2E;
            // Issue LDG for the group after next: first row = t + 1 + PF
            pf_reg = pred_b[(size_t)min(t + 1 + PF + slotp, T_MAX - 1) * stride_t + lane];
            phase ^= 1;
        }

        __syncthreads();
        cur = nxt;
    }

    if (tid == 0) {
        int   sid = 2 * target_lens[b];
        float f0 = alpha[cur][sid + 1];   // state sid-1 (+2 shift)
        float f1 = alpha[cur][sid + 2];   // state sid   (+2 shift)
        float m  = fmaxf(f0, f1);
        float lo = fminf(f0, f1);
        d_per_batch[b] = LN2 * (m + lg2(1.0f + ex2(lo - m)));
    }
}

__global__ void ctc_reduce_kernel(float* __restrict__ out)
{
    const int tid = threadIdx.x;   // 64 threads
    float v = d_per_batch[tid];
    __shared__ float ws[2];
    #pragma unroll
    for (int o = 16; o > 0; o >>= 1)
        v += __shfl_down_sync(0xffffffffu, v, o);
    if ((tid & 31) == 0) ws[tid >> 5] = v;
    __syncthreads();
    if (tid == 0)
        out[0] = -(ws[0] + ws[1]) * (1.0f / (float)B_N);
}

extern "C" void kernel_launch(void* const* d_in, const int* in_sizes, int n_in,
                              void* d_out, int out_size)
{
    const float* prediction  = (const float*)d_in[0];
    const int*   target      = (const int*)  d_in[1];
    const int*   pred_lens   = (const int*)  d_in[2];
    const int*   target_lens = (const int*)  d_in[3];

    ctc_alpha_kernel<<<B_N, NTHREADS>>>(prediction, target, pred_lens, target_lens);
    ctc_reduce_kernel<<<1, B_N>>>((float*)d_out);
}

// round 5
// speedup vs baseline: 3.5220x; 1.1924x over previous
#include <cuda_runtime.h>
#include <math.h>

#define T_MAX 2000
#define B_N   64
#define A_N   32
#define L_N   200
#define S_N   401          // 2*L+1

#define NTHREADS 256
#define NWARPS   8
#define PF       8         // prefetch group depth (rows per LDG burst)

__device__ float d_per_batch[B_N];

__device__ __forceinline__ float ex2(float x) {
    float r; asm("ex2.approx.ftz.f32 %0, %1;" : "=f"(r) : "f"(x)); return r;
}
__device__ __forceinline__ float lg2(float x) {
    float r; asm("lg2.approx.ftz.f32 %0, %1;" : "=f"(r) : "f"(x)); return r;
}

__global__ __launch_bounds__(NTHREADS, 1)
void ctc_alpha_kernel(const float* __restrict__ pred,      // (T,B,A) log-softmax (ln)
                      const int*   __restrict__ target,    // (B,L)
                      const int*   __restrict__ pred_lens,
                      const int*   __restrict__ target_lens)
{
    const int b     = blockIdx.x;
    const int tid   = threadIdx.x;
    const int wid   = tid >> 5;
    const int lane  = tid & 31;
    const int slotp = tid >> 5;      // row-within-group this thread prefetches

    __shared__ float rows[2][PF * A_N]; // double-buffered e-rows, log2 domain
    __shared__ float bnd[2][NWARPS];    // DOUBLE-BUFFERED warp boundaries (race fix)
    __shared__ float fin[2];

    const float LOG2E   = 1.4426950408889634f;
    const float LN2     = 0.6931471805599453f;
    const float NEG_BIG = -1e30f;
    const float L2_EPS  = -13.287712379549449f;  // log2(0.0001)
    const float L2_HALF = -1.0028901240599430f;  // log2(0.499)

    const int Tb = pred_lens[b];
    const int tl = target_lens[b];

    // Per-thread symbol: odd state 2*tid+1 uses target[b][tid]
    const int sym_own = (tid < L_N) ? target[b * L_N + tid] : 0;

    const size_t stride_t = (size_t)B_N * A_N;
    const float* __restrict__ pred_b = pred + (size_t)b * A_N;

    // Register alphas (log2 domain): a0 = state 2*tid, a1 = state 2*tid+1
    float a0 = (tid == 0) ? L2_HALF : L2_EPS;
    float a1 = (tid == 0) ? L2_HALF : L2_EPS;

    // First loop step is t=1, which reads bnd[1][...]; init that buffer.
    if (tid < NWARPS) bnd[1][tid] = (tid == 0) ? NEG_BIG : L2_EPS;

    // Group 0 (rows 1..8) straight to shared
    rows[0][tid] = pred_b[(size_t)min(1 + slotp, T_MAX - 1) * stride_t + lane] * LOG2E;
    // Group 1 (rows 9..16): raw load held in register ~7 steps; scaled at commit
    float pf_reg = pred_b[(size_t)min(9 + slotp, T_MAX - 1) * stride_t + lane];
    __syncthreads();

    int phase = 0;
    for (int t = 1; t < Tb; ++t) {
        const int slot = (t - 1) & (PF - 1);
        const int rb   = t & 1;             // boundary read buffer
        const float* __restrict__ rc = &rows[phase][slot * A_N];

        const float eb = rc[0];         // LDS broadcast
        const float es = rc[sym_own];   // LDS gather, conflict-free (32-word row)

        // a_prev = previous-step odd alpha of left neighbor (state 2*tid-1)
        float ap = __shfl_up_sync(0xffffffffu, a1, 1);
        if (lane == 0) ap = (wid == 0) ? NEG_BIG : bnd[rb][wid - 1];

        // even: x = logaddexp2(a0, ap); na0 = e_blank + x
        float me = fmaxf(a0, ap);
        float le = fminf(a0, ap);
        float x  = me + lg2(1.0f + ex2(le - me));
        float na0 = eb + x;

        // odd: na1 = e_sym + logaddexp2(x, a1)   (x = logadd2 of a[s-1], a[s-2])
        float mo = fmaxf(x, a1);
        float lo = fminf(x, a1);
        float na1 = es + mo + lg2(1.0f + ex2(lo - mo));

        a0 = na0; a1 = na1;
        if (lane == 31) bnd[rb ^ 1][wid] = a1;   // write buffer for step t+1

        if (slot == PF - 1) {
            rows[phase ^ 1][tid] = pf_reg * LOG2E;              // commit next group
            pf_reg = pred_b[(size_t)min(t + 1 + PF + slotp, T_MAX - 1) * stride_t + lane];
            phase ^= 1;
        }

        __syncthreads();   // publishes bnd + rows for next step
    }

    // Extraction: f0 = alpha[2tl-1] (thread tl-1, odd), f1 = alpha[2tl] (thread tl, even)
    if (tid == tl)     fin[1] = a0;
    if (tid == tl - 1) fin[0] = a1;
    __syncthreads();
    if (tid == 0) {
        float f0 = fin[0], f1 = fin[1];
        float m  = fmaxf(f0, f1);
        float lo = fminf(f0, f1);
        d_per_batch[b] = LN2 * (m + lg2(1.0f + ex2(lo - m)));
    }
}

__global__ void ctc_reduce_kernel(float* __restrict__ out)
{
    const int tid = threadIdx.x;   // 64 threads
    float v = d_per_batch[tid];
    __shared__ float ws[2];
    #pragma unroll
    for (int o = 16; o > 0; o >>= 1)
        v += __shfl_down_sync(0xffffffffu, v, o);
    if ((tid & 31) == 0) ws[tid >> 5] = v;
    __syncthreads();
    if (tid == 0)
        out[0] = -(ws[0] + ws[1]) * (1.0f / (float)B_N);
}

extern "C" void kernel_launch(void* const* d_in, const int* in_sizes, int n_in,
                              void* d_out, int out_size)
{
    const float* prediction  = (const float*)d_in[0];
    const int*   target      = (const int*)  d_in[1];
    const int*   pred_lens   = (const int*)  d_in[2];
    const int*   target_lens = (const int*)  d_in[3];

    ctc_alpha_kernel<<<B_N, NTHREADS>>>(prediction, target, pred_lens, target_lens);
    ctc_reduce_kernel<<<1, B_N>>>((float*)d_out);
}

// round 6
// speedup vs baseline: 4.1492x; 1.1781x over previous
#include <cuda_runtime.h>
#include <math.h>

#define T_MAX 2000
#define B_N   64
#define A_N   32
#define L_N   200
#define S_N   401          // 2*L+1

#define NTHREADS 256
#define NWARPS   8
#define PF       8         // prefetch group depth == unroll factor

__device__ float    d_per_batch[B_N];
__device__ unsigned g_ticket = 0;

__device__ __forceinline__ float ex2(float x) {
    float r; asm("ex2.approx.ftz.f32 %0, %1;" : "=f"(r) : "f"(x)); return r;
}
__device__ __forceinline__ float lg2(float x) {
    float r; asm("lg2.approx.ftz.f32 %0, %1;" : "=f"(r) : "f"(x)); return r;
}

__global__ __launch_bounds__(NTHREADS, 1)
void ctc_alpha_kernel(const float* __restrict__ pred,      // (T,B,A) log-softmax (ln)
                      const int*   __restrict__ target,    // (B,L)
                      const int*   __restrict__ pred_lens,
                      const int*   __restrict__ target_lens,
                      float*       __restrict__ out)
{
    const int b     = blockIdx.x;
    const int tid   = threadIdx.x;
    const int wid   = tid >> 5;
    const int lane  = tid & 31;
    const int slotp = tid >> 5;

    __shared__ float rows[2][PF * A_N]; // double-buffered e-rows, log2 domain
    __shared__ float bnd[2][NWARPS];    // double-buffered warp boundaries
    __shared__ float fin[2];

    const float LOG2E   = 1.4426950408889634f;
    const float LN2     = 0.6931471805599453f;
    const float NEG_BIG = -1e30f;
    const float L2_EPS  = -13.287712379549449f;  // log2(0.0001)
    const float L2_HALF = -1.0028901240599430f;  // log2(0.499)

    const int Tb   = pred_lens[b];
    const int TbM1 = Tb - 1;
    const int tl   = target_lens[b];
    const bool is_f1 = (tid == tl);       // holds alpha[2tl]   in a0
    const bool is_f0 = (tid == tl - 1);   // holds alpha[2tl-1] in a1

    const int sym_own = (tid < L_N) ? target[b * L_N + tid] : 0;

    const size_t stride_t = (size_t)B_N * A_N;
    const float* __restrict__ pred_b = pred + (size_t)b * A_N;

    // Register alphas (log2): a0 = state 2*tid, a1 = state 2*tid+1
    float a0 = (tid == 0) ? L2_HALF : L2_EPS;
    float a1 = (tid == 0) ? L2_HALF : L2_EPS;
    float f0c = a1, f1c = a0;            // captured finals (valid if Tb == 1)

    // t=1 reads bnd[1][...]
    if (tid < NWARPS) bnd[1][tid] = (tid == 0) ? NEG_BIG : L2_EPS;

    rows[0][tid] = pred_b[(size_t)min(1 + slotp, T_MAX - 1) * stride_t + lane] * LOG2E;
    float pf_reg = pred_b[(size_t)min(9 + slotp, T_MAX - 1) * stride_t + lane];
    __syncthreads();

    int phase = 0;
    for (int base = 1; base < Tb; base += PF) {
        #pragma unroll
        for (int u = 0; u < PF; ++u) {
            const int t  = base + u;           // base-1 is a multiple of 8 -> slot == u
            const int rb = (1 + u) & 1;        // t parity (base is odd)
            const float* __restrict__ rc = &rows[phase][u * A_N];

            const float eb = rc[0];
            const float es = rc[sym_own];

            float ap = __shfl_up_sync(0xffffffffu, a1, 1);
            if (lane == 0) ap = (wid == 0) ? NEG_BIG : bnd[rb][wid - 1];

            // odd state: direct 3-way logaddexp2(a1, a0, ap) -- independent of even
            float h  = fmaxf(a0, ap);
            float l  = fminf(a0, ap);
            float m3 = fmaxf(h, a1);
            float s2 = fminf(h, a1);
            float sum3 = 1.0f + ex2(s2 - m3) + ex2(l - m3);
            float na1 = es + m3 + lg2(sum3);

            // even state: 2-way logaddexp2(a0, ap)
            float na0 = eb + h + lg2(1.0f + ex2(l - h));

            a0 = na0; a1 = na1;
            if (lane == 31) bnd[rb ^ 1][wid] = a1;

            // capture final alphas at t == Tb-1 (loop may overrun harmlessly)
            const bool last = (t == TbM1);
            f1c = (last && is_f1) ? a0 : f1c;
            f0c = (last && is_f0) ? a1 : f0c;

            if (u == PF - 1) {
                rows[phase ^ 1][tid] = pf_reg * LOG2E;
                pf_reg = pred_b[(size_t)min(t + 1 + PF + slotp, T_MAX - 1) * stride_t + lane];
                phase ^= 1;
            }
            __syncthreads();
        }
    }

    if (is_f1) fin[1] = f1c;
    if (is_f0) fin[0] = f0c;
    __syncthreads();

    if (tid == 0) {
        float f0 = fin[0], f1 = fin[1];
        float m  = fmaxf(f0, f1);
        float lo = fminf(f0, f1);
        d_per_batch[b] = LN2 * (m + lg2(1.0f + ex2(lo - m)));
        __threadfence();
        unsigned old = atomicAdd(&g_ticket, 1u);
        if (old == B_N - 1) {
            float s = 0.0f;
            #pragma unroll 4
            for (int i = 0; i < B_N; ++i)
                s += __ldcg(&d_per_batch[i]);   // fixed order -> deterministic
            out[0] = -s * (1.0f / (float)B_N);
            g_ticket = 0;                       // reset for next graph replay
        }
    }
}

extern "C" void kernel_launch(void* const* d_in, const int* in_sizes, int n_in,
                              void* d_out, int out_size)
{
    const float* prediction  = (const float*)d_in[0];
    const int*   target      = (const int*)  d_in[1];
    const int*   pred_lens   = (const int*)  d_in[2];
    const int*   target_lens = (const int*)  d_in[3];

    ctc_alpha_kernel<<<B_N, NTHREADS>>>(prediction, target, pred_lens, target_lens,
                                        (float*)d_out);
}

// round 8
// speedup vs baseline: 4.4197x; 1.0652x over previous
#include <cuda_runtime.h>
#include <math.h>

#define T_MAX 2000
#define B_N   64
#define A_N   32
#define L_N   200
#define S_N   401          // 2*L+1

#define NTHREADS 128
#define NWARPS   4
#define PF       8         // prefetch group depth == unroll factor

__device__ float    d_per_batch[B_N];
__device__ unsigned g_ticket = 0;

__device__ __forceinline__ float ex2(float x) {
    float r; asm("ex2.approx.ftz.f32 %0, %1;" : "=f"(r) : "f"(x)); return r;
}
__device__ __forceinline__ float lg2(float x) {
    float r; asm("lg2.approx.ftz.f32 %0, %1;" : "=f"(r) : "f"(x)); return r;
}

// logaddexp2 helpers (log2 domain, branch-free, safe: ex2 arg <= 0)
__device__ __forceinline__ float lse2_2(float x, float y) {
    float h = fmaxf(x, y), l = fminf(x, y);
    return h + lg2(1.0f + ex2(l - h));
}
__device__ __forceinline__ float lse2_3(float x, float y, float z) {
    float h  = fmaxf(x, y), l = fminf(x, y);
    float m  = fmaxf(h, z), s = fminf(h, z);
    return m + lg2(1.0f + ex2(s - m) + ex2(l - m));
}

__global__ __launch_bounds__(NTHREADS, 1)
void ctc_alpha_kernel(const float* __restrict__ pred,      // (T,B,A) log-softmax (ln)
                      const int*   __restrict__ target,    // (B,L)
                      const int*   __restrict__ pred_lens,
                      const int*   __restrict__ target_lens,
                      float*       __restrict__ out)
{
    const int b    = blockIdx.x;
    const int tid  = threadIdx.x;
    const int wid  = tid >> 5;
    const int lane = tid & 31;

    __shared__ float rows[2][PF * A_N]; // double-buffered e-rows, log2 domain
    __shared__ float bnd[2][NWARPS];    // double-buffered warp boundaries
    __shared__ float fin[2];

    const float LOG2E   = 1.4426950408889634f;
    const float LN2     = 0.6931471805599453f;
    const float NEG_BIG = -1e30f;
    const float L2_EPS  = -13.287712379549449f;  // log2(0.0001)
    const float L2_HALF = -1.0028901240599430f;  // log2(0.499)

    const int Tb   = pred_lens[b];
    const int TbM1 = Tb - 1;
    const int tl   = target_lens[b];

    // Final-state owners: f0 = alpha[2tl-1] (odd), f1 = alpha[2tl] (even)
    const int  s0 = 2 * tl - 1, s1 = 2 * tl;
    const bool f0_here = (tid == (s0 >> 2));
    const bool f0_isB  = ((s0 >> 1) & 1) != 0;
    const bool f1_here = (tid == (s1 >> 2));
    const bool f1_isB  = ((s1 >> 1) & 1) != 0;

    // Symbols for the two odd states this thread owns (coalesced int2)
    int symA = 0, symB = 0;
    if (tid < L_N / 2) {
        int2 sv = ((const int2*)(target + b * L_N))[tid];
        symA = sv.x; symB = sv.y;
    }

    const size_t stride_t = (size_t)B_N * A_N;
    const float* __restrict__ pred_b = pred + (size_t)b * A_N;

    // Register alphas (log2): pair A = states (4t, 4t+1), pair B = (4t+2, 4t+3)
    float a0 = (tid == 0) ? L2_HALF : L2_EPS;
    float a1 = (tid == 0) ? L2_HALF : L2_EPS;
    float b0 = L2_EPS;
    float b1 = L2_EPS;
    float f0c = L2_EPS, f1c = L2_EPS;

    // t=1 reads bnd[1][...]: warp w lane0 needs state 128w-1 at t=0
    if (tid < NWARPS) bnd[1][tid] = (tid == 0) ? NEG_BIG : L2_EPS;

    // Each thread handles 2 elements of the 256-float row group
    const int roff0 = tid >> 5;        // 0..3
    const int roff1 = roff0 + 4;       // 4..7

    rows[0][tid]       = pred_b[(size_t)min(1 + roff0, T_MAX - 1) * stride_t + lane] * LOG2E;
    rows[0][tid + 128] = pred_b[(size_t)min(1 + roff1, T_MAX - 1) * stride_t + lane] * LOG2E;
    float pf0 = pred_b[(size_t)min(9 + roff0, T_MAX - 1) * stride_t + lane];
    float pf1 = pred_b[(size_t)min(9 + roff1, T_MAX - 1) * stride_t + lane];
    __syncthreads();

    int phase = 0;
    for (int base = 1; base < Tb; base += PF) {
        #pragma unroll
        for (int u = 0; u < PF; ++u) {
            const int t  = base + u;
            const int rb = (1 + u) & 1;       // t parity (base odd)
            const float* __restrict__ rc = &rows[phase][u * A_N];

            const float eb  = rc[0];
            const float esA = rc[symA];
            const float esB = rc[symB];

            // pair A left-neighbor: previous thread's pair-B odd alpha
            float ap = __shfl_up_sync(0xffffffffu, b1, 1);
            if (lane == 0) ap = (wid == 0) ? NEG_BIG : bnd[rb][wid - 1];

            // pair B left-neighbor: own pair-A old odd alpha (register!)
            const float bp = a1;

            float na0 = eb  + lse2_2(a0, ap);
            float na1 = esA + lse2_3(a0, ap, a1);
            float nb0 = eb  + lse2_2(b0, bp);
            float nb1 = esB + lse2_3(b0, bp, b1);

            a0 = na0; a1 = na1; b0 = nb0; b1 = nb1;
            if (lane == 31) bnd[rb ^ 1][wid] = b1;

            if (t == TbM1) {
                if (f0_here) f0c = f0_isB ? b1 : a1;
                if (f1_here) f1c = f1_isB ? b0 : a0;
            }

            if (u == PF - 1) {
                rows[phase ^ 1][tid]       = pf0 * LOG2E;
                rows[phase ^ 1][tid + 128] = pf1 * LOG2E;
                pf0 = pred_b[(size_t)min(t + 1 + PF + roff0, T_MAX - 1) * stride_t + lane];
                pf1 = pred_b[(size_t)min(t + 1 + PF + roff1, T_MAX - 1) * stride_t + lane];
                phase ^= 1;
            }
            __syncthreads();
        }
    }

    if (f0_here) fin[0] = f0c;
    if (f1_here) fin[1] = f1c;
    __syncthreads();

    if (tid == 0) {
        d_per_batch[b] = LN2 * lse2_2(fin[0], fin[1]);
        __threadfence();
        unsigned old = atomicAdd(&g_ticket, 1u);
        if (old == B_N - 1) {
            float s = 0.0f;
            #pragma unroll 4
            for (int i = 0; i < B_N; ++i)
                s += __ldcg(&d_per_batch[i]);   // fixed order -> deterministic
            out[0] = -s * (1.0f / (float)B_N);
            g_ticket = 0;                       // reset for next graph replay
        }
    }
}

extern "C" void kernel_launch(void* const* d_in, const int* in_sizes, int n_in,
                              void* d_out, int out_size)
{
    const float* prediction  = (const float*)d_in[0];
    const int*   target      = (const int*)  d_in[1];
    const int*   pred_lens   = (const int*)  d_in[2];
    const int*   target_lens = (const int*)  d_in[3];

    ctc_alpha_kernel<<<B_N, NTHREADS>>>(prediction, target, pred_lens, target_lens,
                                        (float*)d_out);
}